// round 3
// baseline (speedup 1.0000x reference)
#include <cuda_runtime.h>
#include <math.h>

// Problem constants
#define Bn   8
#define Cn   64
#define Hn   256
#define Wn   256
#define OCn  32     // C/2
#define OHn  254
#define OWn  254

// Stage-1 tiling
#define GOC   8              // output channels per group
#define NOCG  (OCn / GOC)    // 4 groups
#define NOP   (GOC / 2)      // 4 o-pairs (packed f32x2)
#define PX    4              // output pixels (columns) per thread
#define TXD   64             // threads in x
#define TYD   4              // threads in y (output rows per tile)
#define NTHR  (TXD * TYD)    // 256
#define ICC   8              // input channels per smem chunk
#define NICC  (Cn / ICC)     // 8 chunks
#define XS_ROWS    (TYD + 2)          // 6 rows (halo)
#define XS_STRIDE  260                // 258 needed, padded for float4 alignment
#define XS_FLOATS  (ICC * XS_ROWS * XS_STRIDE)   // 12480
#define WS_FLOATS  (GOC * Cn * 9)                // 4608
#define SMEM_FLOATS (XS_FLOATS + WS_FLOATS)      // 17088
#define SMEM_BYTES  (SMEM_FLOATS * 4)            // 68352
#define ROWTILES   64        // 64 * TYD = 256 >= 254 output rows

__device__ float g_partial[Bn * ROWTILES];
__device__ float g_kern[Bn][9];

// ---- packed f32x2 helpers (sm_103a; ptxas will not auto-fuse these) --------
__device__ __forceinline__ unsigned long long pk_dup(float a) {
    unsigned long long r;
    asm("mov.b64 %0, {%1, %1};" : "=l"(r) : "f"(a));
    return r;
}
__device__ __forceinline__ void fma2(unsigned long long& d,
                                     unsigned long long a,
                                     unsigned long long b) {
    asm("fma.rn.f32x2 %0, %1, %2, %0;" : "+l"(d) : "l"(a), "l"(b));
}
__device__ __forceinline__ void unpk(float& lo, float& hi, unsigned long long v) {
    asm("mov.b64 {%0, %1}, %2;" : "=f"(lo), "=f"(hi) : "l"(v));
}

// ---------------------------------------------------------------------------
// Stage 1: conv(3x3, valid) -> relu -> weighted (w_fc) spatial sum, per batch.
// Packed over output-channel pairs: acc lanes = (o even, o odd).
// Weights staged in smem transposed to [ic][k][o] so a float2 LDS yields the
// packed (w[o], w[o+1]) operand directly.
// ---------------------------------------------------------------------------
__global__ __launch_bounds__(NTHR, 2)
void conv_sigma_kernel(const float* __restrict__ x,
                       const float* __restrict__ w_sigma,
                       const float* __restrict__ w_fc) {
    extern __shared__ float smem[];
    float* xs = smem;               // XS_FLOATS
    float* ws = smem + XS_FLOATS;   // WS_FLOATS, layout [Cn][9][GOC]

    const int tx  = threadIdx.x;
    const int ty  = threadIdx.y;
    const int tid = ty * TXD + tx;
    const int rt  = blockIdx.x;     // row tile
    const int b   = blockIdx.y;     // batch
    const int r0  = rt * TYD;       // first output row of tile

    float partial = 0.0f;

    for (int ocg = 0; ocg < NOCG; ++ocg) {
        __syncthreads();  // protect ws from previous group's readers
        // Load + transpose this oc-group's weights: wg[o][ic][k] -> ws[(ic*9+k)*GOC+o]
        const float* wg = w_sigma + ocg * WS_FLOATS;
        for (int i = tid; i < WS_FLOATS; i += NTHR) {
            const int o   = i / (Cn * 9);
            const int rem = i - o * (Cn * 9);      // ic*9 + k
            ws[rem * GOC + o] = wg[i];
        }

        unsigned long long acc2[NOP][PX];
        #pragma unroll
        for (int op = 0; op < NOP; ++op)
            #pragma unroll
            for (int p = 0; p < PX; ++p) acc2[op][p] = 0ull;

        for (int icc = 0; icc < NICC; ++icc) {
            __syncthreads();  // protect xs from previous chunk's readers
            // Cooperative load of x chunk: [ICC][XS_ROWS][XS_STRIDE]
            const float* xb = x + ((b * Cn + icc * ICC) << 16);  // H*W = 65536
            for (int i = tid; i < XS_FLOATS; i += NTHR) {
                int ic  = i / (XS_ROWS * XS_STRIDE);
                int rem = i - ic * (XS_ROWS * XS_STRIDE);
                int row = rem / XS_STRIDE;
                int col = rem - row * XS_STRIDE;
                int gr = min(r0 + row, Hn - 1);
                int gc = min(col, Wn - 1);
                xs[i] = xb[(ic << 16) + (gr << 8) + gc];
            }
            __syncthreads();

            for (int ic = 0; ic < ICC; ++ic) {
                // Load 3 rows x (PX+2) columns of x, duplicate into b64 lanes.
                unsigned long long xd[3][PX + 2];
                const float* xrb = xs + ic * (XS_ROWS * XS_STRIDE) + tx * PX;
                #pragma unroll
                for (int kh = 0; kh < 3; ++kh) {
                    const float4 v  = *(const float4*)(xrb + (ty + kh) * XS_STRIDE);
                    const float2 v2 = *(const float2*)(xrb + (ty + kh) * XS_STRIDE + 4);
                    xd[kh][0] = pk_dup(v.x);  xd[kh][1] = pk_dup(v.y);
                    xd[kh][2] = pk_dup(v.z);  xd[kh][3] = pk_dup(v.w);
                    xd[kh][4] = pk_dup(v2.x); xd[kh][5] = pk_dup(v2.y);
                }
                const int icg = icc * ICC + ic;
                const float* wbase = ws + icg * 9 * GOC;
                #pragma unroll
                for (int op = 0; op < NOP; ++op) {
                    #pragma unroll
                    for (int kh = 0; kh < 3; ++kh)
                        #pragma unroll
                        for (int kw = 0; kw < 3; ++kw) {
                            const float2 wv2 =
                                *(const float2*)(wbase + (kh * 3 + kw) * GOC + op * 2);
                            unsigned long long wp;
                            asm("mov.b64 %0, {%1, %2};"
                                : "=l"(wp) : "f"(wv2.x), "f"(wv2.y));
                            #pragma unroll
                            for (int p = 0; p < PX; ++p)
                                fma2(acc2[op][p], xd[kh][p + kw], wp);
                        }
                }
            }
        }

        // Epilogue: relu -> weight by w_fc -> thread partial (mask invalid px)
        const int row = r0 + ty;
        const bool rowok = (row < OHn);
        #pragma unroll
        for (int op = 0; op < NOP; ++op) {
            const float wfc0 = __ldg(&w_fc[ocg * GOC + op * 2 + 0]);
            const float wfc1 = __ldg(&w_fc[ocg * GOC + op * 2 + 1]);
            float s0 = 0.0f, s1 = 0.0f;
            #pragma unroll
            for (int p = 0; p < PX; ++p) {
                const int col = tx * PX + p;
                float a0, a1;
                unpk(a0, a1, acc2[op][p]);
                if (rowok && col < OWn) {
                    s0 += fmaxf(a0, 0.0f);
                    s1 += fmaxf(a1, 0.0f);
                }
            }
            partial += wfc0 * s0 + wfc1 * s1;
        }
    }

    // Deterministic block reduction (reuse smem)
    __syncthreads();
    float* red = smem;
    red[tid] = partial;
    __syncthreads();
    for (int s = NTHR / 2; s > 0; s >>= 1) {
        if (tid < s) red[tid] += red[tid + s];
        __syncthreads();
    }
    if (tid == 0) g_partial[b * ROWTILES + rt] = red[0];
}

// ---------------------------------------------------------------------------
// Stage 1b: finish reduction -> sigmoid -> Gaussian 3x3 kernel per batch.
// Note: 1/(sqrt(2pi)*s) prefactor cancels in normalization.
// ---------------------------------------------------------------------------
__global__ void sigma_kernel(const float* __restrict__ b_fc) {
    const int b = threadIdx.x;
    if (b >= Bn) return;
    float S = 0.0f;
    for (int i = 0; i < ROWTILES; ++i) S += g_partial[b * ROWTILES + i];
    const float dot = S * (1.0f / (float)(OHn * OWn)) + b_fc[0];
    const float sig = 1.0f / (1.0f + expf(-dot));
    const float s   = fmaxf(sig, 1e-4f);
    const float inv2 = 1.0f / (s * s);
    const float e1 = expf(-0.5f * inv2);   // d^2 = 1 (edges)
    const float e2 = expf(-inv2);          // d^2 = 2 (corners)
    const float inorm = 1.0f / (1.0f + 4.0f * e1 + 4.0f * e2);
    g_kern[b][0] = e2 * inorm; g_kern[b][1] = e1 * inorm; g_kern[b][2] = e2 * inorm;
    g_kern[b][3] = e1 * inorm; g_kern[b][4] = inorm;      g_kern[b][5] = e1 * inorm;
    g_kern[b][6] = e2 * inorm; g_kern[b][7] = e1 * inorm; g_kern[b][8] = e2 * inorm;
}

// ---------------------------------------------------------------------------
// Stage 2: per-sample 3x3 Gaussian blur, reflect pad 1, stride 2.
// out[c][b][oh][ow]. Each thread computes 4 consecutive ow (one STG.128);
// per input row: 2x LDG.128 (cols 2ow0..2ow0+7) + 1 scalar (col 2ow0-1).
// ---------------------------------------------------------------------------
__global__ __launch_bounds__(256)
void blur_kernel(const float* __restrict__ x, float* __restrict__ out) {
    const int idx = blockIdx.x * blockDim.x + threadIdx.x;   // over total/4
    const int ow4 = idx & 31;            // group of 4 output columns
    const int oh  = (idx >> 5) & 127;
    const int b   = (idx >> 12) & 7;
    const int c   = idx >> 15;
    const int ow0 = ow4 << 2;            // first output col (multiple of 4)

    const float* kb = g_kern[b];
    const float k0 = kb[0], k1 = kb[1], k2 = kb[2];
    const float k3 = kb[3], k4 = kb[4], k5 = kb[5];
    const float k6 = kb[6], k7 = kb[7], k8 = kb[8];

    const float* xb = x + (((b * Cn) + c) << 16);

    int rm = 2 * oh - 1;
    const int r0 = (rm < 0) ? 1 : rm;    // reflect (only oh==0)
    const int r1 = 2 * oh;
    const int r2 = 2 * oh + 1;           // max 255, in range

    const int cbase = ow0 << 1;          // 2*ow0, multiple of 8 -> 16B aligned

    float a0[9], a1[9], a2[9];
    {
        const float* p = xb + (r0 << 8) + cbase;
        const float4 va = *(const float4*)(p);
        const float4 vb = *(const float4*)(p + 4);
        // col cbase-1; reflect to col 1 == va.y when cbase==0
        a0[0] = (cbase == 0) ? va.y : p[-1];
        a0[1] = va.x; a0[2] = va.y; a0[3] = va.z; a0[4] = va.w;
        a0[5] = vb.x; a0[6] = vb.y; a0[7] = vb.z; a0[8] = vb.w;
    }
    {
        const float* p = xb + (r1 << 8) + cbase;
        const float4 va = *(const float4*)(p);
        const float4 vb = *(const float4*)(p + 4);
        a1[0] = (cbase == 0) ? va.y : p[-1];
        a1[1] = va.x; a1[2] = va.y; a1[3] = va.z; a1[4] = va.w;
        a1[5] = vb.x; a1[6] = vb.y; a1[7] = vb.z; a1[8] = vb.w;
    }
    {
        const float* p = xb + (r2 << 8) + cbase;
        const float4 va = *(const float4*)(p);
        const float4 vb = *(const float4*)(p + 4);
        a2[0] = (cbase == 0) ? va.y : p[-1];
        a2[1] = va.x; a2[2] = va.y; a2[3] = va.z; a2[4] = va.w;
        a2[5] = vb.x; a2[6] = vb.y; a2[7] = vb.z; a2[8] = vb.w;
    }

    float4 res;
    float* rp = (float*)&res;
    #pragma unroll
    for (int p = 0; p < 4; ++p) {
        const int m = p << 1;   // a[m] = col 2p-1, a[m+1] = 2p, a[m+2] = 2p+1
        rp[p] = k0 * a0[m] + k1 * a0[m + 1] + k2 * a0[m + 2]
              + k3 * a1[m] + k4 * a1[m + 1] + k5 * a1[m + 2]
              + k6 * a2[m] + k7 * a2[m + 1] + k8 * a2[m + 2];
    }

    // out index: c*(8*128*128) + b*(128*128) + oh*128 + ow0  (16B aligned)
    *(float4*)(out + (idx << 2)) = res;
}

// ---------------------------------------------------------------------------
extern "C" void kernel_launch(void* const* d_in, const int* in_sizes, int n_in,
                              void* d_out, int out_size) {
    const float* x       = (const float*)d_in[0];
    const float* w_sigma = (const float*)d_in[1];
    const float* w_fc    = (const float*)d_in[2];
    const float* b_fc    = (const float*)d_in[3];
    float* out = (float*)d_out;

    cudaFuncSetAttribute(conv_sigma_kernel,
                         cudaFuncAttributeMaxDynamicSharedMemorySize, SMEM_BYTES);

    conv_sigma_kernel<<<dim3(ROWTILES, Bn), dim3(TXD, TYD), SMEM_BYTES>>>(x, w_sigma, w_fc);
    sigma_kernel<<<1, 32>>>(b_fc);

    const int total4 = Cn * Bn * 128 * 128 / 4;   // 2,097,152 threads
    blur_kernel<<<total4 / 256, 256>>>(x, out);
}

// round 6
// speedup vs baseline: 2.9130x; 2.9130x over previous
#include <cuda_runtime.h>
#include <math.h>

// Problem constants
#define Bn   8
#define Cn   64
#define Hn   256
#define Wn   256
#define OCn  32     // C/2
#define OHn  254
#define OWn  254

// Stage-1 tiling
#define GOC   8              // output channels per block (grid.z group)
#define NOCG  (OCn / GOC)    // 4 groups -> grid.z
#define NOP   (GOC / 2)      // 4 o-pairs (packed f32x2)
#define PX    4              // output pixels (columns) per thread
#define TXD   64             // threads in x
#define TYD   4              // threads in y (output rows per tile)
#define NTHR  (TXD * TYD)    // 256
#define ICC   8              // input channels per smem chunk
#define NICC  (Cn / ICC)     // 8 chunks
#define XS_ROWS    (TYD + 2)          // 6 rows (halo)
#define XS_STRIDE  260                // 258 needed, padded for float4 alignment
#define XS_FLOATS  (ICC * XS_ROWS * XS_STRIDE)   // 12480
#define WS_FLOATS  (GOC * Cn * 9)                // 4608
#define SMEM_FLOATS (XS_FLOATS + WS_FLOATS)      // 17088
#define SMEM_BYTES  (SMEM_FLOATS * 4)            // 68352
#define ROWTILES   64        // 64 * TYD = 256 >= 254 output rows

__device__ float g_partial[Bn * NOCG * ROWTILES];
__device__ float g_kern[Bn][9];

// ---- packed f32x2 helpers (sm_103a; ptxas will not auto-fuse these) --------
__device__ __forceinline__ unsigned long long pk_dup(float a) {
    unsigned long long r;
    asm("mov.b64 %0, {%1, %1};" : "=l"(r) : "f"(a));
    return r;
}
__device__ __forceinline__ void fma2(unsigned long long& d,
                                     unsigned long long a,
                                     unsigned long long b) {
    asm("fma.rn.f32x2 %0, %1, %2, %0;" : "+l"(d) : "l"(a), "l"(b));
}
__device__ __forceinline__ void unpk(float& lo, float& hi, unsigned long long v) {
    asm("mov.b64 {%0, %1}, %2;" : "=f"(lo), "=f"(hi) : "l"(v));
}

// ---------------------------------------------------------------------------
// Stage 1: conv(3x3, valid) -> relu -> weighted (w_fc) spatial sum.
// Block = (row tile rt, batch b, oc-group ocg). x loaded ONCE per block.
// Packed f32x2 over output-channel pairs; weights in smem as [ic][tap][o]
// so an aligned 8-byte LDS yields the packed (w[o], w[o+1]) operand directly.
// launch_bounds kept at (256,2): forcing 3 blocks caps regs ~85 and risks
// spilling the unrolled FMA2 loop to local memory (R4 timeout suspect).
// ---------------------------------------------------------------------------
__global__ __launch_bounds__(NTHR, 2)
void conv_sigma_kernel(const float* __restrict__ x,
                       const float* __restrict__ w_sigma,
                       const float* __restrict__ w_fc) {
    extern __shared__ float smem[];
    float* xs = smem;               // XS_FLOATS, layout [ic*6+row][XS_STRIDE]
    float* ws = smem + XS_FLOATS;   // WS_FLOATS, layout [Cn][9][GOC]

    const int tx  = threadIdx.x;
    const int ty  = threadIdx.y;
    const int tid = ty * TXD + tx;
    const int rt  = blockIdx.x;     // row tile
    const int b   = blockIdx.y;     // batch
    const int ocg = blockIdx.z;     // oc group
    const int r0  = rt * TYD;       // first output row of tile

    // Load + transpose this oc-group's weights: wg[o][ic][k] -> ws[(ic*9+k)*GOC+o]
    {
        const float* wg = w_sigma + (ocg * GOC) * (Cn * 9);
        for (int i = tid; i < WS_FLOATS; i += NTHR) {
            const int o   = i / (Cn * 9);
            const int rem = i - o * (Cn * 9);      // ic*9 + k
            ws[rem * GOC + o] = wg[i];
        }
    }

    unsigned long long acc2[NOP][PX];
    #pragma unroll
    for (int op = 0; op < NOP; ++op)
        #pragma unroll
        for (int p = 0; p < PX; ++p) acc2[op][p] = 0ull;

    // Fill-loop invariants
    const int rr0 = ty;                  // 0..3 (row-subgroup)
    const int c4  = tx << 2;             // 0..252 step 4
    float partial = 0.0f;

    for (int icc = 0; icc < NICC; ++icc) {
        __syncthreads();  // protect xs/ws from previous readers
        // ---- x fill: 48 rows (ic,row) x 258 cols, clamped replicate ----
        const float* xb = x + ((b * Cn + icc * ICC) << 16);  // H*W = 65536
        #pragma unroll
        for (int g = 0; g < 12; ++g) {
            const int rr  = g * 4 + rr0;           // 0..47
            const int ic  = rr / XS_ROWS;          // 0..7
            const int row = rr - ic * XS_ROWS;     // 0..5
            const int gr  = min(r0 + row, Hn - 1);
            const float4 v = *(const float4*)(xb + (ic << 16) + (gr << 8) + c4);
            *(float4*)(xs + rr * XS_STRIDE + c4) = v;
        }
        // tail: cols 256,257 clamp to col 255
        if (tid < 96) {
            const int rr   = tid >> 1;
            const int colt = 256 + (tid & 1);
            const int ic   = rr / XS_ROWS;
            const int row  = rr - ic * XS_ROWS;
            const int gr   = min(r0 + row, Hn - 1);
            xs[rr * XS_STRIDE + colt] = xb[(ic << 16) + (gr << 8) + 255];
        }
        __syncthreads();

        // ---- Compute ----
        #pragma unroll
        for (int ic = 0; ic < ICC; ++ic) {
            float xr[3][PX + 2];
            const float* xrb = xs + ic * (XS_ROWS * XS_STRIDE) + tx * PX;
            #pragma unroll
            for (int kh = 0; kh < 3; ++kh) {
                const float4 v  = *(const float4*)(xrb + (ty + kh) * XS_STRIDE);
                const float2 v2 = *(const float2*)(xrb + (ty + kh) * XS_STRIDE + 4);
                xr[kh][0] = v.x;  xr[kh][1] = v.y;  xr[kh][2] = v.z;
                xr[kh][3] = v.w;  xr[kh][4] = v2.x; xr[kh][5] = v2.y;
            }
            const float* wbase = ws + (icc * ICC + ic) * 9 * GOC;
            #pragma unroll
            for (int kh = 0; kh < 3; ++kh) {
                #pragma unroll
                for (int kw = 0; kw < 3; ++kw) {
                    const unsigned long long xd0 = pk_dup(xr[kh][kw]);
                    const unsigned long long xd1 = pk_dup(xr[kh][kw + 1]);
                    const unsigned long long xd2 = pk_dup(xr[kh][kw + 2]);
                    const unsigned long long xd3 = pk_dup(xr[kh][kw + 3]);
                    // 32B-aligned base -> direct 8B loads of packed weight pairs
                    const unsigned long long* wrow =
                        (const unsigned long long*)(wbase + (kh * 3 + kw) * GOC);
                    #pragma unroll
                    for (int op = 0; op < NOP; ++op) {
                        const unsigned long long wp = wrow[op];  // LDS.64 broadcast
                        fma2(acc2[op][0], xd0, wp);
                        fma2(acc2[op][1], xd1, wp);
                        fma2(acc2[op][2], xd2, wp);
                        fma2(acc2[op][3], xd3, wp);
                    }
                }
            }
        }
    }

    // Epilogue: relu -> weight by w_fc -> thread partial (mask invalid px)
    {
        const int row = r0 + ty;
        const bool rowok = (row < OHn);
        #pragma unroll
        for (int op = 0; op < NOP; ++op) {
            const float wfc0 = __ldg(&w_fc[ocg * GOC + op * 2 + 0]);
            const float wfc1 = __ldg(&w_fc[ocg * GOC + op * 2 + 1]);
            float s0 = 0.0f, s1 = 0.0f;
            #pragma unroll
            for (int p = 0; p < PX; ++p) {
                const int col = tx * PX + p;
                float a0, a1;
                unpk(a0, a1, acc2[op][p]);
                if (rowok && col < OWn) {
                    s0 += fmaxf(a0, 0.0f);
                    s1 += fmaxf(a1, 0.0f);
                }
            }
            partial += wfc0 * s0 + wfc1 * s1;
        }
    }

    // Deterministic block reduction (reuse smem)
    __syncthreads();
    float* red = smem;
    red[tid] = partial;
    __syncthreads();
    for (int s = NTHR / 2; s > 0; s >>= 1) {
        if (tid < s) red[tid] += red[tid + s];
        __syncthreads();
    }
    if (tid == 0)
        g_partial[(b * NOCG + ocg) * ROWTILES + rt] = red[0];
}

// ---------------------------------------------------------------------------
// Stage 1b: finish reduction -> sigmoid -> Gaussian 3x3 kernel per batch.
// Note: 1/(sqrt(2pi)*s) prefactor cancels in normalization.
// ---------------------------------------------------------------------------
__global__ void sigma_kernel(const float* __restrict__ b_fc) {
    const int b = threadIdx.x;
    if (b >= Bn) return;
    float S = 0.0f;
    for (int i = 0; i < NOCG * ROWTILES; ++i)
        S += g_partial[b * (NOCG * ROWTILES) + i];
    const float dot = S * (1.0f / (float)(OHn * OWn)) + b_fc[0];
    const float sig = 1.0f / (1.0f + expf(-dot));
    const float s   = fmaxf(sig, 1e-4f);
    const float inv2 = 1.0f / (s * s);
    const float e1 = expf(-0.5f * inv2);   // d^2 = 1 (edges)
    const float e2 = expf(-inv2);          // d^2 = 2 (corners)
    const float inorm = 1.0f / (1.0f + 4.0f * e1 + 4.0f * e2);
    g_kern[b][0] = e2 * inorm; g_kern[b][1] = e1 * inorm; g_kern[b][2] = e2 * inorm;
    g_kern[b][3] = e1 * inorm; g_kern[b][4] = inorm;      g_kern[b][5] = e1 * inorm;
    g_kern[b][6] = e2 * inorm; g_kern[b][7] = e1 * inorm; g_kern[b][8] = e2 * inorm;
}

// ---------------------------------------------------------------------------
// Stage 2: per-sample 3x3 Gaussian blur, reflect pad 1, stride 2.
// out[c][b][oh][ow]. Each thread computes 4 consecutive ow (one STG.128);
// per input row: 2x LDG.128 (cols 2ow0..2ow0+7) + 1 scalar (col 2ow0-1).
// ---------------------------------------------------------------------------
__global__ __launch_bounds__(256)
void blur_kernel(const float* __restrict__ x, float* __restrict__ out) {
    const int idx = blockIdx.x * blockDim.x + threadIdx.x;   // over total/4
    const int ow4 = idx & 31;            // group of 4 output columns
    const int oh  = (idx >> 5) & 127;
    const int b   = (idx >> 12) & 7;
    const int c   = idx >> 15;
    const int ow0 = ow4 << 2;            // first output col (multiple of 4)

    const float* kb = g_kern[b];
    const float k0 = kb[0], k1 = kb[1], k2 = kb[2];
    const float k3 = kb[3], k4 = kb[4], k5 = kb[5];
    const float k6 = kb[6], k7 = kb[7], k8 = kb[8];

    const float* xb = x + (((b * Cn) + c) << 16);

    int rm = 2 * oh - 1;
    const int r0 = (rm < 0) ? 1 : rm;    // reflect (only oh==0)
    const int r1 = 2 * oh;
    const int r2 = 2 * oh + 1;           // max 255, in range

    const int cbase = ow0 << 1;          // 2*ow0, multiple of 8 -> 16B aligned

    float a0[9], a1[9], a2[9];
    {
        const float* p = xb + (r0 << 8) + cbase;
        const float4 va = *(const float4*)(p);
        const float4 vb = *(const float4*)(p + 4);
        a0[0] = (cbase == 0) ? va.y : p[-1];   // reflect col -1 -> col 1
        a0[1] = va.x; a0[2] = va.y; a0[3] = va.z; a0[4] = va.w;
        a0[5] = vb.x; a0[6] = vb.y; a0[7] = vb.z; a0[8] = vb.w;
    }
    {
        const float* p = xb + (r1 << 8) + cbase;
        const float4 va = *(const float4*)(p);
        const float4 vb = *(const float4*)(p + 4);
        a1[0] = (cbase == 0) ? va.y : p[-1];
        a1[1] = va.x; a1[2] = va.y; a1[3] = va.z; a1[4] = va.w;
        a1[5] = vb.x; a1[6] = vb.y; a1[7] = vb.z; a1[8] = vb.w;
    }
    {
        const float* p = xb + (r2 << 8) + cbase;
        const float4 va = *(const float4*)(p);
        const float4 vb = *(const float4*)(p + 4);
        a2[0] = (cbase == 0) ? va.y : p[-1];
        a2[1] = va.x; a2[2] = va.y; a2[3] = va.z; a2[4] = va.w;
        a2[5] = vb.x; a2[6] = vb.y; a2[7] = vb.z; a2[8] = vb.w;
    }

    float4 res;
    float* rp = (float*)&res;
    #pragma unroll
    for (int p = 0; p < 4; ++p) {
        const int m = p << 1;   // a[m] = col 2p-1, a[m+1] = 2p, a[m+2] = 2p+1
        rp[p] = k0 * a0[m] + k1 * a0[m + 1] + k2 * a0[m + 2]
              + k3 * a1[m] + k4 * a1[m + 1] + k5 * a1[m + 2]
              + k6 * a2[m] + k7 * a2[m + 1] + k8 * a2[m + 2];
    }

    *(float4*)(out + (idx << 2)) = res;
}

// ---------------------------------------------------------------------------
extern "C" void kernel_launch(void* const* d_in, const int* in_sizes, int n_in,
                              void* d_out, int out_size) {
    const float* x       = (const float*)d_in[0];
    const float* w_sigma = (const float*)d_in[1];
    const float* w_fc    = (const float*)d_in[2];
    const float* b_fc    = (const float*)d_in[3];
    float* out = (float*)d_out;

    cudaFuncSetAttribute(conv_sigma_kernel,
                         cudaFuncAttributeMaxDynamicSharedMemorySize, SMEM_BYTES);

    conv_sigma_kernel<<<dim3(ROWTILES, Bn, NOCG), dim3(TXD, TYD), SMEM_BYTES>>>(
        x, w_sigma, w_fc);
    sigma_kernel<<<1, 32>>>(b_fc);

    const int total4 = Cn * Bn * 128 * 128 / 4;   // 2,097,152 threads
    blur_kernel<<<total4 / 256, 256>>>(x, out);
}

// round 17
// speedup vs baseline: 6.3767x; 2.1891x over previous
#include <cuda_runtime.h>
#include <math.h>

// Problem constants
#define Bn   8
#define Cn   64
#define Hn   256
#define Wn   256
#define OCn  32     // C/2
#define OHn  254
#define OWn  254

// Stage-1 tiling: block = 2 output rows x 256 cols, 8 warps, all 32 oc.
#define ROWTILES 128         // 2 output rows per tile -> 128 tiles
#define TROWS 2
#define XROWS 4              // TROWS + 2 halo rows (VALID conv)
#define ICC   8              // input channels per chunk = one k8 tile
#define NCH   (Cn / ICC)     // 8 chunks
#define ROW_STRIDE 260       // floats per row (256 written, 257 read max)
#define IC_PLANE  (XROWS * ROW_STRIDE + 8)   // 1048 -> bank offset 24/ic (conflict-free A)
#define CHUNK_FLOATS (ICC * IC_PLANE)        // 8384
#define XS_FLOATS (2 * CHUNK_FLOATS)         // 16768 (double-buffered)
#define WS_IC_STRIDE 296                     // 9*32=288 used; bank offset 8/ic (conflict-free B)
#define WS_FLOATS (Cn * WS_IC_STRIDE)        // 18944
#define SMEM_FLOATS (XS_FLOATS + WS_FLOATS)  // 35712
#define SMEM_BYTES  (SMEM_FLOATS * 4)        // 142848

__device__ float g_partial[Bn * ROWTILES];
__device__ float g_kern[Bn][9];

// ---- cp.async helpers ------------------------------------------------------
__device__ __forceinline__ void cp16(float* smem_dst, const float* gsrc) {
    unsigned saddr = (unsigned)__cvta_generic_to_shared(smem_dst);
    asm volatile("cp.async.cg.shared.global [%0], [%1], 16;"
                 :: "r"(saddr), "l"(gsrc) : "memory");
}
#define CP_COMMIT() asm volatile("cp.async.commit_group;" ::: "memory")
#define CP_WAIT1()  asm volatile("cp.async.wait_group 1;" ::: "memory")
#define CP_WAIT0()  asm volatile("cp.async.wait_group 0;" ::: "memory")

// ---- tf32 helpers ----------------------------------------------------------
__device__ __forceinline__ unsigned f2tf32(float f) {
    unsigned u;
    asm("cvt.rna.tf32.f32 %0, %1;" : "=r"(u) : "f"(f));
    return u;
}
// m16n8k8 row.col f32 += tf32*tf32
__device__ __forceinline__ void mma8(float* c,
                                     unsigned a0, unsigned a1, unsigned a2, unsigned a3,
                                     unsigned b0, unsigned b1) {
    asm volatile(
        "mma.sync.aligned.m16n8k8.row.col.f32.tf32.tf32.f32 "
        "{%0,%1,%2,%3}, {%4,%5,%6,%7}, {%8,%9}, {%0,%1,%2,%3};"
        : "+f"(c[0]), "+f"(c[1]), "+f"(c[2]), "+f"(c[3])
        : "r"(a0), "r"(a1), "r"(a2), "r"(a3), "r"(b0), "r"(b1));
}

// ---------------------------------------------------------------------------
// Stage 1: conv(3x3, valid) -> relu -> w_fc-weighted spatial sum, per batch.
// Implicit GEMM: for each tap (kh,kw): C[pixel, oc] += A[pixel, ic] B[ic, oc],
// ic chunked by 8 (one m16n8k8 k-tile), tf32 mma with fp32 accum.
//   A fragment: pixel m = col within warp segment; k = ic (plane stride 1048).
//   B in smem as ws[ic][tap][oc] (tf32 bits pre-converted).
// Warp w: row = r0 + (w>>2), col segment (w&3)*64 = 4 m-tiles x 4 n-tiles.
// ---------------------------------------------------------------------------
__global__ __launch_bounds__(256)
void conv_sigma_kernel(const float* __restrict__ x,
                       const float* __restrict__ w_sigma,
                       const float* __restrict__ w_fc) {
    extern __shared__ float smem[];
    float* xs = smem;                // 2 stages
    float* ws = smem + XS_FLOATS;    // [Cn][tap][oc] tf32 bits

    const int tx   = threadIdx.x;    // 0..63
    const int ty   = threadIdx.y;    // 0..3
    const int tid  = ty * 64 + tx;
    const int w    = tid >> 5;       // warp 0..7
    const int lane = tid & 31;
    const int rt   = blockIdx.x;     // row tile (2 rows)
    const int b    = blockIdx.y;     // batch
    const int r0   = rt * TROWS;

    // ws fill + transpose + tf32 convert: w_sigma[oc][ic][tap] -> ws[ic*296+tap*32+oc]
    for (int i = tid; i < OCn * Cn * 9; i += 256) {
        const int oc  = i / 576;
        const int rem = i - oc * 576;        // ic*9 + tap
        const int ic  = rem / 9;
        const int tap = rem - ic * 9;
        ws[ic * WS_IC_STRIDE + tap * 32 + oc] = __uint_as_float(f2tf32(w_sigma[i]));
    }

    float C[4][4][4];                // [mt][nt][frag]
    #pragma unroll
    for (int mt = 0; mt < 4; ++mt)
        #pragma unroll
        for (int nt = 0; nt < 4; ++nt)
            #pragma unroll
            for (int q = 0; q < 4; ++q) C[mt][nt][q] = 0.0f;

    const int c4 = tx << 2;          // 0..252 step 4
    const float* xbase = x + ((b * Cn) << 16);

    // Prefetch chunk 0: 32 (ic,row) rows x 256 cols, 8 cp16 per thread
    {
        #pragma unroll
        for (int j = 0; j < 8; ++j) {
            const int rowj = ty + 4 * j;           // 0..31
            const int ic   = rowj >> 2;
            const int r    = rowj & 3;
            const int gr   = min(r0 + r, Hn - 1);
            cp16(xs + ic * IC_PLANE + r * ROW_STRIDE + c4,
                 xbase + (ic << 16) + (gr << 8) + c4);
        }
        CP_COMMIT();
    }

    const int wr   = w >> 2;         // warp row 0/1
    const int cseg = (w & 3) * 64;   // warp col segment
    const int gid  = lane >> 2;      // groupID 0..7
    const int tig  = lane & 3;       // threadID-in-group 0..3
    const int koff = tig * IC_PLANE;

    for (int ch = 0; ch < NCH; ++ch) {
        if (ch < NCH - 1) {
            float* dst = xs + ((ch + 1) & 1) * CHUNK_FLOATS;
            const float* xb = xbase + (((ch + 1) * ICC) << 16);
            #pragma unroll
            for (int j = 0; j < 8; ++j) {
                const int rowj = ty + 4 * j;
                const int ic   = rowj >> 2;
                const int r    = rowj & 3;
                const int gr   = min(r0 + r, Hn - 1);
                cp16(dst + ic * IC_PLANE + r * ROW_STRIDE + c4,
                     xb + (ic << 16) + (gr << 8) + c4);
            }
            CP_COMMIT();
            CP_WAIT1();
        } else {
            CP_WAIT0();
        }
        __syncthreads();   // current stage fully visible

        const float* st = xs + (ch & 1) * CHUNK_FLOATS;
        const float* wchunk = ws + (ch * ICC) * WS_IC_STRIDE;

        #pragma unroll
        for (int kh = 0; kh < 3; ++kh) {
            #pragma unroll
            for (int kw = 0; kw < 3; ++kw) {
                const int tap = kh * 3 + kw;
                // B fragments: b0 = B[k=tig][n=nt*8+gid], b1 = B[k=tig+4][...]
                unsigned b0[4], b1[4];
                const float* wrow = wchunk + tap * 32 + gid;
                #pragma unroll
                for (int nt = 0; nt < 4; ++nt) {
                    b0[nt] = __float_as_uint(wrow[tig * WS_IC_STRIDE + nt * 8]);
                    b1[nt] = __float_as_uint(wrow[(tig + 4) * WS_IC_STRIDE + nt * 8]);
                }
                // A base: pixel row (wr+kh), col cseg + kw + m
                const float* abase = st + (wr + kh) * ROW_STRIDE + cseg + kw + gid;
                #pragma unroll
                for (int mt = 0; mt < 4; ++mt) {
                    const float* ap = abase + mt * 16;
                    const unsigned a0 = f2tf32(ap[koff]);                    // m=gid,  k=tig
                    const unsigned a1 = f2tf32(ap[8 + koff]);                // m=gid+8,k=tig
                    const unsigned a2 = f2tf32(ap[koff + 4 * IC_PLANE]);     // m=gid,  k=tig+4
                    const unsigned a3 = f2tf32(ap[8 + koff + 4 * IC_PLANE]); // m=gid+8,k=tig+4
                    #pragma unroll
                    for (int nt = 0; nt < 4; ++nt)
                        mma8(C[mt][nt], a0, a1, a2, a3, b0[nt], b1[nt]);
                }
            }
        }
        __syncthreads();   // readers done before next prefetch overwrites
    }

    // Epilogue: relu -> w_fc weighting -> thread partial (mask edge pixels)
    float partial = 0.0f;
    {
        const int row = r0 + wr;
        const bool rowok = (row < OHn);
        #pragma unroll
        for (int nt = 0; nt < 4; ++nt) {
            const int oc = nt * 8 + 2 * tig;
            const float f0 = __ldg(&w_fc[oc]);
            const float f1 = __ldg(&w_fc[oc + 1]);
            #pragma unroll
            for (int mt = 0; mt < 4; ++mt) {
                const int col = cseg + mt * 16 + gid;    // pixel col (m), +8 for c2/c3
                if (rowok && col < OWn)
                    partial += f0 * fmaxf(C[mt][nt][0], 0.0f)
                             + f1 * fmaxf(C[mt][nt][1], 0.0f);
                if (rowok && col + 8 < OWn)
                    partial += f0 * fmaxf(C[mt][nt][2], 0.0f)
                             + f1 * fmaxf(C[mt][nt][3], 0.0f);
            }
        }
    }

    // Deterministic block reduction (reuse smem)
    __syncthreads();
    float* red = smem;
    red[tid] = partial;
    __syncthreads();
    for (int s = 128; s > 0; s >>= 1) {
        if (tid < s) red[tid] += red[tid + s];
        __syncthreads();
    }
    if (tid == 0) g_partial[b * ROWTILES + rt] = red[0];
}

// ---------------------------------------------------------------------------
// Stage 1b: finish reduction -> sigmoid -> Gaussian 3x3 kernel per batch.
// ---------------------------------------------------------------------------
__global__ void sigma_kernel(const float* __restrict__ b_fc) {
    const int b = threadIdx.x;
    if (b >= Bn) return;
    float S = 0.0f;
    for (int i = 0; i < ROWTILES; ++i) S += g_partial[b * ROWTILES + i];
    const float dot = S * (1.0f / (float)(OHn * OWn)) + b_fc[0];
    const float sig = 1.0f / (1.0f + expf(-dot));
    const float s   = fmaxf(sig, 1e-4f);
    const float inv2 = 1.0f / (s * s);
    const float e1 = expf(-0.5f * inv2);   // d^2 = 1 (edges)
    const float e2 = expf(-inv2);          // d^2 = 2 (corners)
    const float inorm = 1.0f / (1.0f + 4.0f * e1 + 4.0f * e2);
    g_kern[b][0] = e2 * inorm; g_kern[b][1] = e1 * inorm; g_kern[b][2] = e2 * inorm;
    g_kern[b][3] = e1 * inorm; g_kern[b][4] = inorm;      g_kern[b][5] = e1 * inorm;
    g_kern[b][6] = e2 * inorm; g_kern[b][7] = e1 * inorm; g_kern[b][8] = e2 * inorm;
}

// ---------------------------------------------------------------------------
// Stage 2: per-sample 3x3 Gaussian blur, reflect pad 1, stride 2.
// ---------------------------------------------------------------------------
__global__ __launch_bounds__(256)
void blur_kernel(const float* __restrict__ x, float* __restrict__ out) {
    const int idx = blockIdx.x * blockDim.x + threadIdx.x;   // over total/4
    const int oh  = (idx >> 5) & 127;
    const int b   = (idx >> 12) & 7;
    const int c   = idx >> 15;
    const int ow0 = (idx & 31) << 2;     // first output col (multiple of 4)

    const float* kb = g_kern[b];
    const float k0 = kb[0], k1 = kb[1], k2 = kb[2];
    const float k3 = kb[3], k4 = kb[4], k5 = kb[5];
    const float k6 = kb[6], k7 = kb[7], k8 = kb[8];

    const float* xb = x + (((b * Cn) + c) << 16);

    int rm = 2 * oh - 1;
    const int r0 = (rm < 0) ? 1 : rm;    // reflect (only oh==0)
    const int r1 = 2 * oh;
    const int r2 = 2 * oh + 1;

    const int cbase = ow0 << 1;          // 16B aligned

    float a0[9], a1[9], a2[9];
    {
        const float* p = xb + (r0 << 8) + cbase;
        const float4 va = *(const float4*)(p);
        const float4 vb = *(const float4*)(p + 4);
        a0[0] = (cbase == 0) ? va.y : p[-1];
        a0[1] = va.x; a0[2] = va.y; a0[3] = va.z; a0[4] = va.w;
        a0[5] = vb.x; a0[6] = vb.y; a0[7] = vb.z; a0[8] = vb.w;
    }
    {
        const float* p = xb + (r1 << 8) + cbase;
        const float4 va = *(const float4*)(p);
        const float4 vb = *(const float4*)(p + 4);
        a1[0] = (cbase == 0) ? va.y : p[-1];
        a1[1] = va.x; a1[2] = va.y; a1[3] = va.z; a1[4] = va.w;
        a1[5] = vb.x; a1[6] = vb.y; a1[7] = vb.z; a1[8] = vb.w;
    }
    {
        const float* p = xb + (r2 << 8) + cbase;
        const float4 va = *(const float4*)(p);
        const float4 vb = *(const float4*)(p + 4);
        a2[0] = (cbase == 0) ? va.y : p[-1];
        a2[1] = va.x; a2[2] = va.y; a2[3] = va.z; a2[4] = va.w;
        a2[5] = vb.x; a2[6] = vb.y; a2[7] = vb.z; a2[8] = vb.w;
    }

    float4 res;
    float* rp = (float*)&res;
    #pragma unroll
    for (int p = 0; p < 4; ++p) {
        const int m = p << 1;
        rp[p] = k0 * a0[m] + k1 * a0[m + 1] + k2 * a0[m + 2]
              + k3 * a1[m] + k4 * a1[m + 1] + k5 * a1[m + 2]
              + k6 * a2[m] + k7 * a2[m + 1] + k8 * a2[m + 2];
    }

    *(float4*)(out + (idx << 2)) = res;
}

// ---------------------------------------------------------------------------
extern "C" void kernel_launch(void* const* d_in, const int* in_sizes, int n_in,
                              void* d_out, int out_size) {
    const float* x       = (const float*)d_in[0];
    const float* w_sigma = (const float*)d_in[1];
    const float* w_fc    = (const float*)d_in[2];
    const float* b_fc    = (const float*)d_in[3];
    float* out = (float*)d_out;

    cudaFuncSetAttribute(conv_sigma_kernel,
                         cudaFuncAttributeMaxDynamicSharedMemorySize, SMEM_BYTES);

    conv_sigma_kernel<<<dim3(ROWTILES, Bn), dim3(64, 4), SMEM_BYTES>>>(
        x, w_sigma, w_fc);
    sigma_kernel<<<1, 32>>>(b_fc);

    const int total4 = Cn * Bn * 128 * 128 / 4;   // 2,097,152 threads
    blur_kernel<<<total4 / 256, 256>>>(x, out);
}